// round 2
// baseline (speedup 1.0000x reference)
#include <cuda_runtime.h>
#include <math.h>
#include <stdint.h>

// ---------------------------------------------------------------------------
// Problem constants
// ---------------------------------------------------------------------------
constexpr int B_   = 2;
constexpr int S_   = 2048;
constexpr int D_   = 2048;
constexpr int H_   = 16;
constexpr int HD_  = 128;
constexpr int PAST_= 2048;
constexpr int SKV_ = 4096;   // PAST + S
constexpr int M_X  = B_ * S_;        // 4096 rows of x
constexpr int TD_  = 3 * D_;         // 6144
constexpr float SCALE_ = 0.08838834764831845f;  // 1/sqrt(128)

// ---------------------------------------------------------------------------
// Scratch (static device memory; no cudaMalloc allowed).  64 MB total.
// ---------------------------------------------------------------------------
__device__ float g_q[(size_t)B_ * H_ * S_ * HD_];            // 8.39 M floats
__device__ float g_attn[(size_t)B_ * S_ * D_];               // 8.39 M floats

// ---------------------------------------------------------------------------
// SIMT GEMM mainloop: 128x128 tile, K-step 8, 256 threads,
// each thread owns an 8x8 micro-tile using the split {t*4, 64+t*4} layout.
// NT: C[m][n] = sum_k A[m][k] * B[n][k]   (both operands K-contiguous)
// ---------------------------------------------------------------------------
__device__ __forceinline__ void gemm_nt_tile(
    const float* __restrict__ A,    // row-tile base
    const float* __restrict__ Bp,   // col-tile base
    int lda, int ldb, int K,
    float (&acc)[8][8])
{
    __shared__ float As[8][128];
    __shared__ float Bs[8][128];
    const int tid = threadIdx.x;
    const int tx  = tid & 15;
    const int ty  = tid >> 4;
    const int lr  = tid >> 1;          // load row within tile (0..127)
    const int lk  = (tid & 1) * 4;     // k offset 0 or 4

#pragma unroll
    for (int i = 0; i < 8; i++)
#pragma unroll
        for (int j = 0; j < 8; j++) acc[i][j] = 0.f;

    for (int kt = 0; kt < K; kt += 8) {
        float4 av = *reinterpret_cast<const float4*>(A  + (size_t)lr * lda + kt + lk);
        float4 bv = *reinterpret_cast<const float4*>(Bp + (size_t)lr * ldb + kt + lk);
        __syncthreads();   // previous iteration's readers done
        As[lk + 0][lr] = av.x; As[lk + 1][lr] = av.y;
        As[lk + 2][lr] = av.z; As[lk + 3][lr] = av.w;
        Bs[lk + 0][lr] = bv.x; Bs[lk + 1][lr] = bv.y;
        Bs[lk + 2][lr] = bv.z; Bs[lk + 3][lr] = bv.w;
        __syncthreads();
#pragma unroll
        for (int kk = 0; kk < 8; kk++) {
            float a[8], b[8];
#pragma unroll
            for (int i = 0; i < 4; i++) {
                a[i]     = As[kk][ty * 4 + i];
                a[i + 4] = As[kk][64 + ty * 4 + i];
                b[i]     = Bs[kk][tx * 4 + i];
                b[i + 4] = Bs[kk][64 + tx * 4 + i];
            }
#pragma unroll
            for (int i = 0; i < 8; i++)
#pragma unroll
                for (int j = 0; j < 8; j++)
                    acc[i][j] += a[i] * b[j];
        }
    }
}

__device__ __forceinline__ int micro_idx(int t, int i) {
    return (i < 4) ? (t * 4 + i) : (64 + t * 4 + (i - 4));
}

// ---------------------------------------------------------------------------
// Kernel 1: copy past_k/past_v into rows [0,PAST) of each (b,h) slice of the
// k/v outputs (layout [B,H,SKV,HD]).
// ---------------------------------------------------------------------------
__global__ void __launch_bounds__(256)
k_copy_past(const float4* __restrict__ pk, const float4* __restrict__ pv,
            float4* __restrict__ ko, float4* __restrict__ vo)
{
    size_t i = (size_t)blockIdx.x * blockDim.x + threadIdx.x;
    constexpr size_t n4    = (size_t)B_ * H_ * PAST_ * HD_ / 4;  // 2097152
    constexpr size_t chunk = (size_t)PAST_ * HD_ / 4;            // 65536
    constexpr size_t dchunk= (size_t)SKV_  * HD_ / 4;            // 131072
    if (i < n4) {
        size_t bh  = i / chunk;
        size_t rem = i - bh * chunk;
        size_t dst = bh * dchunk + rem;
        ko[dst] = pk[i];
        vo[dst] = pv[i];
    }
}

// ---------------------------------------------------------------------------
// Kernel 2: qkv = x @ qkv_w^T + qkv_b, scattered:
//   q -> g_q [B,H,S,HD];  k,v -> kout/vout [B,H,SKV,HD] rows PAST_..
// ---------------------------------------------------------------------------
__global__ void __launch_bounds__(256, 2)
k_qkv(const float* __restrict__ x, const float* __restrict__ w,
      const float* __restrict__ bias,
      float* __restrict__ kout, float* __restrict__ vout)
{
    float acc[8][8];
    gemm_nt_tile(x + (size_t)blockIdx.y * 128 * D_,
                 w + (size_t)blockIdx.x * 128 * D_,
                 D_, D_, D_, acc);
    const int tx = threadIdx.x & 15;
    const int ty = threadIdx.x >> 4;
#pragma unroll
    for (int i = 0; i < 8; i++) {
        int m = blockIdx.y * 128 + micro_idx(ty, i);
        int b = m >> 11;           // / S_
        int s = m & (S_ - 1);
#pragma unroll
        for (int j = 0; j < 8; j++) {
            int n = blockIdx.x * 128 + micro_idx(tx, j);
            float v = acc[i][j] + bias[n];
            int sec = n >> 11;     // 0=q 1=k 2=v
            int d0  = n & (D_ - 1);
            int h   = d0 >> 7;
            int hd  = d0 & 127;
            if (sec == 0) {
                g_q[(((size_t)(b * H_ + h)) * S_ + s) * HD_ + hd] = v;
            } else {
                float* dst = (sec == 1) ? kout : vout;
                dst[(((size_t)(b * H_ + h)) * SKV_ + (PAST_ + s)) * HD_ + hd] = v;
            }
        }
    }
}

// ---------------------------------------------------------------------------
// Kernel 3: fused flash attention (fp32, online softmax).
//   One block = 128 q rows x one (b,h). Loops kv in tiles of 128.
//   smem: Qs [d][128] | KPs (Ks [d][128], reused as Ps [m][132]) | Vs [kv][128]
// ---------------------------------------------------------------------------
constexpr int FL_QS  = 0;                 // floats
constexpr int FL_KPS = 128 * 128;         // 16384
constexpr int FL_VS  = FL_KPS + 128 * 132;// 16384 + 16896 = 33280
constexpr int FL_SMEM_FLOATS = FL_VS + 128 * 128;           // 49664
constexpr int FL_SMEM_BYTES  = FL_SMEM_FLOATS * 4;          // 198656

__global__ void __launch_bounds__(256, 1)
k_flash(const float* __restrict__ kin, const float* __restrict__ vin)
{
    extern __shared__ float sm[];
    float* Qs  = sm + FL_QS;
    float* KPs = sm + FL_KPS;
    float* Vs  = sm + FL_VS;

    const int z   = blockIdx.y;           // b*H + h
    const int tid = threadIdx.x;
    const int tx  = tid & 15;
    const int ty  = tid >> 4;
    const int lr  = tid >> 1;             // 0..127 (load row)
    const int ld0 = (tid & 1) * 64;       // d half

    // --- load Q tile transposed into Qs[d][row] ---
    const float* qg = g_q + (size_t)z * S_ * HD_ + (size_t)blockIdx.x * 128 * HD_;
#pragma unroll
    for (int c = 0; c < 16; c++) {
        float4 v = *reinterpret_cast<const float4*>(qg + (size_t)lr * HD_ + ld0 + c * 4);
        Qs[(ld0 + c * 4 + 0) * 128 + lr] = v.x;
        Qs[(ld0 + c * 4 + 1) * 128 + lr] = v.y;
        Qs[(ld0 + c * 4 + 2) * 128 + lr] = v.z;
        Qs[(ld0 + c * 4 + 3) * 128 + lr] = v.w;
    }

    float mrow[8], lrow[8], o[8][8];
#pragma unroll
    for (int i = 0; i < 8; i++) {
        mrow[i] = -3.0e38f;
        lrow[i] = 0.f;
#pragma unroll
        for (int j = 0; j < 8; j++) o[i][j] = 0.f;
    }

    const float* kz = kin + (size_t)z * SKV_ * HD_;
    const float* vz = vin + (size_t)z * SKV_ * HD_;

    for (int t = 0; t < SKV_ / 128; t++) {
        __syncthreads();  // previous tile's smem readers done (also guards Q load, iter 0)
        // --- load K tile transposed (Ks[d][kv]) and V tile direct (Vs[kv][d]) ---
        const float* krow = kz + (size_t)(t * 128 + lr) * HD_ + ld0;
        const float* vrow = vz + (size_t)(t * 128 + lr) * HD_ + ld0;
#pragma unroll
        for (int c = 0; c < 16; c++) {
            float4 kv4 = *reinterpret_cast<const float4*>(krow + c * 4);
            KPs[(ld0 + c * 4 + 0) * 128 + lr] = kv4.x;
            KPs[(ld0 + c * 4 + 1) * 128 + lr] = kv4.y;
            KPs[(ld0 + c * 4 + 2) * 128 + lr] = kv4.z;
            KPs[(ld0 + c * 4 + 3) * 128 + lr] = kv4.w;
            float4 vv4 = *reinterpret_cast<const float4*>(vrow + c * 4);
            *reinterpret_cast<float4*>(&Vs[lr * 128 + ld0 + c * 4]) = vv4;
        }
        __syncthreads();

        // --- scores s = (Q k^T) * SCALE : 8x8 micro, K = 128 ---
        float s[8][8];
#pragma unroll
        for (int i = 0; i < 8; i++)
#pragma unroll
            for (int j = 0; j < 8; j++) s[i][j] = 0.f;
        for (int kk = 0; kk < 128; kk++) {
            float a[8], b[8];
#pragma unroll
            for (int i = 0; i < 4; i++) {
                a[i]     = Qs[kk * 128 + ty * 4 + i];
                a[i + 4] = Qs[kk * 128 + 64 + ty * 4 + i];
                b[i]     = KPs[kk * 128 + tx * 4 + i];
                b[i + 4] = KPs[kk * 128 + 64 + tx * 4 + i];
            }
#pragma unroll
            for (int i = 0; i < 8; i++)
#pragma unroll
                for (int j = 0; j < 8; j++)
                    s[i][j] += a[i] * b[j];
        }

        // --- online softmax update (row groups = 16 lanes sharing ty) ---
#pragma unroll
        for (int i = 0; i < 8; i++) {
            float tmax = -3.0e38f;
#pragma unroll
            for (int j = 0; j < 8; j++) {
                s[i][j] *= SCALE_;
                tmax = fmaxf(tmax, s[i][j]);
            }
#pragma unroll
            for (int ofs = 8; ofs > 0; ofs >>= 1)
                tmax = fmaxf(tmax, __shfl_xor_sync(0xffffffffu, tmax, ofs));
            float M    = fmaxf(mrow[i], tmax);
            float corr = __expf(mrow[i] - M);
            mrow[i] = M;
            float rsum = 0.f;
#pragma unroll
            for (int j = 0; j < 8; j++) {
                s[i][j] = __expf(s[i][j] - M);
                rsum += s[i][j];
            }
#pragma unroll
            for (int ofs = 8; ofs > 0; ofs >>= 1)
                rsum += __shfl_xor_sync(0xffffffffu, rsum, ofs);
            lrow[i] = lrow[i] * corr + rsum;
#pragma unroll
            for (int j = 0; j < 8; j++) o[i][j] *= corr;
        }

        __syncthreads();  // everyone done reading Ks before P overwrites it
        // --- write P into KPs as Ps[m][132] (pad kills read-side conflicts) ---
#pragma unroll
        for (int i = 0; i < 8; i++) {
            int m = micro_idx(ty, i);
#pragma unroll
            for (int j = 0; j < 8; j++) {
                int n = micro_idx(tx, j);
                KPs[m * 132 + n] = s[i][j];
            }
        }
        __syncthreads();

        // --- O += P @ V : K = 128 over kv cols ---
        for (int kk = 0; kk < 128; kk++) {
            float a[8], b[8];
#pragma unroll
            for (int i = 0; i < 4; i++) {
                a[i]     = KPs[(ty * 4 + i) * 132 + kk];
                a[i + 4] = KPs[(64 + ty * 4 + i) * 132 + kk];
                b[i]     = Vs[kk * 128 + tx * 4 + i];
                b[i + 4] = Vs[kk * 128 + 64 + tx * 4 + i];
            }
#pragma unroll
            for (int i = 0; i < 8; i++)
#pragma unroll
                for (int j = 0; j < 8; j++)
                    o[i][j] += a[i] * b[j];
        }
    }

    // --- finalize: O /= l, write to g_attn as [b, s, h, hd] ---
    const int b = z >> 4;
    const int h = z & 15;
#pragma unroll
    for (int i = 0; i < 8; i++) {
        float inv = 1.0f / lrow[i];
        int s_idx = blockIdx.x * 128 + micro_idx(ty, i);
#pragma unroll
        for (int j = 0; j < 8; j++) {
            int hd = micro_idx(tx, j);
            g_attn[(((size_t)(b * S_ + s_idx)) * H_ + h) * HD_ + hd] = o[i][j] * inv;
        }
    }
}

// ---------------------------------------------------------------------------
// Kernel 4: out = attn @ out_w^T + out_b
// ---------------------------------------------------------------------------
__global__ void __launch_bounds__(256, 2)
k_out(const float* __restrict__ w, const float* __restrict__ bias,
      float* __restrict__ out)
{
    float acc[8][8];
    gemm_nt_tile(g_attn + (size_t)blockIdx.y * 128 * D_,
                 w      + (size_t)blockIdx.x * 128 * D_,
                 D_, D_, D_, acc);
    const int tx = threadIdx.x & 15;
    const int ty = threadIdx.x >> 4;
#pragma unroll
    for (int i = 0; i < 8; i++) {
        int m = blockIdx.y * 128 + micro_idx(ty, i);
#pragma unroll
        for (int j = 0; j < 8; j++) {
            int n = blockIdx.x * 128 + micro_idx(tx, j);
            out[(size_t)m * D_ + n] = acc[i][j] + bias[n];
        }
    }
}

// ---------------------------------------------------------------------------
// Launcher: d_out = [ out (B*S*D) | k (B*H*SKV*HD) | v (B*H*SKV*HD) ]
// ---------------------------------------------------------------------------
extern "C" void kernel_launch(void* const* d_in, const int* in_sizes, int n_in,
                              void* d_out, int out_size)
{
    const float* x      = (const float*)d_in[0];
    const float* past_k = (const float*)d_in[1];
    const float* past_v = (const float*)d_in[2];
    const float* qkv_w  = (const float*)d_in[3];
    const float* qkv_b  = (const float*)d_in[4];
    const float* out_w  = (const float*)d_in[5];
    const float* out_b  = (const float*)d_in[6];

    float* out  = (float*)d_out;
    float* kout = out  + (size_t)B_ * S_ * D_;
    float* vout = kout + (size_t)B_ * H_ * SKV_ * HD_;

    // allow 194 KB dynamic smem for the flash kernel (idempotent, capture-safe)
    cudaFuncSetAttribute(k_flash, cudaFuncAttributeMaxDynamicSharedMemorySize,
                         FL_SMEM_BYTES);

    // 1) seed k/v cache with the past
    k_copy_past<<<8192, 256>>>((const float4*)past_k, (const float4*)past_v,
                               (float4*)kout, (float4*)vout);
    // 2) fused qkv gemm + bias + scatter
    k_qkv<<<dim3(TD_ / 128, M_X / 128), 256>>>(x, qkv_w, qkv_b, kout, vout);
    // 3) fused flash attention -> g_attn
    k_flash<<<dim3(S_ / 128, B_ * H_), 256, FL_SMEM_BYTES>>>(kout, vout);
    // 4) output projection
    k_out<<<dim3(D_ / 128, M_X / 128), 256>>>(out_w, out_b, out);
}

// round 4
// speedup vs baseline: 3.6078x; 3.6078x over previous
#include <cuda_runtime.h>
#include <math.h>
#include <stdint.h>

constexpr int B_    = 2;
constexpr int S_    = 2048;
constexpr int D_    = 2048;
constexpr int H_    = 16;
constexpr int HD_   = 128;
constexpr int PAST_ = 2048;
constexpr int SKV_  = 4096;
constexpr int M_X   = B_ * S_;     // 4096
constexpr int TD_   = 3 * D_;      // 6144
constexpr float SCALE_ = 0.08838834764831845f;

// tf32 operand buffers (bits in uint32)
__device__ uint32_t g_xt  [(size_t)M_X * D_];
__device__ uint32_t g_wq  [(size_t)TD_ * D_];
__device__ uint32_t g_wo  [(size_t)D_ * D_];
__device__ uint32_t g_q   [(size_t)B_ * H_ * S_ * HD_];    // q * SCALE
__device__ uint32_t g_kt  [(size_t)B_ * H_ * SKV_ * HD_];
__device__ uint32_t g_vt  [(size_t)B_ * H_ * SKV_ * HD_];
__device__ uint32_t g_attn[(size_t)M_X * D_];

__device__ __forceinline__ uint32_t f32_tf32(float x) {
    uint32_t u; asm("cvt.rna.tf32.f32 %0, %1;" : "=r"(u) : "f"(x)); return u;
}
__device__ __forceinline__ void mma8(float* d, const uint32_t* a, const uint32_t* b) {
    asm volatile(
        "mma.sync.aligned.m16n8k8.row.col.f32.tf32.tf32.f32 "
        "{%0,%1,%2,%3},{%4,%5,%6,%7},{%8,%9},{%0,%1,%2,%3};"
        : "+f"(d[0]), "+f"(d[1]), "+f"(d[2]), "+f"(d[3])
        : "r"(a[0]), "r"(a[1]), "r"(a[2]), "r"(a[3]), "r"(b[0]), "r"(b[1]));
}
__device__ __forceinline__ void cp16(uint32_t dst, const void* src) {
    asm volatile("cp.async.cg.shared.global [%0], [%1], 16;" :: "r"(dst), "l"(src));
}
#define CP_COMMIT() asm volatile("cp.async.commit_group;")
#define CP_WAIT0()  asm volatile("cp.async.wait_group 0;")
__device__ __forceinline__ uint32_t smaddr(const void* p) {
    return (uint32_t)__cvta_generic_to_shared(p);
}

// ---------------- convert f32 -> tf32 into selected global buffer ----------
__global__ void __launch_bounds__(256)
k_cvt(const float4* __restrict__ src, int which, int n4)
{
    uint4* dst = (which == 0) ? reinterpret_cast<uint4*>(g_xt)
               : (which == 1) ? reinterpret_cast<uint4*>(g_wq)
                              : reinterpret_cast<uint4*>(g_wo);
    for (int i = blockIdx.x * 256 + threadIdx.x; i < n4; i += gridDim.x * 256) {
        float4 v = src[i];
        uint4 o = { f32_tf32(v.x), f32_tf32(v.y), f32_tf32(v.z), f32_tf32(v.w) };
        dst[i] = o;
    }
}

// ---------------- past copy: f32 outputs + tf32 mirrors --------------------
__global__ void __launch_bounds__(256)
k_copy_past(const float4* __restrict__ pk, const float4* __restrict__ pv,
            float4* __restrict__ ko, float4* __restrict__ vo)
{
    size_t i = (size_t)blockIdx.x * 256 + threadIdx.x;
    constexpr size_t n4     = (size_t)B_ * H_ * PAST_ * HD_ / 4;
    constexpr size_t chunk  = (size_t)PAST_ * HD_ / 4;
    constexpr size_t dchunk = (size_t)SKV_  * HD_ / 4;
    if (i < n4) {
        size_t bh = i / chunk, rem = i - bh * chunk, dst = bh * dchunk + rem;
        float4 kv = pk[i], vv = pv[i];
        ko[dst] = kv; vo[dst] = vv;
        uint4 kt = { f32_tf32(kv.x), f32_tf32(kv.y), f32_tf32(kv.z), f32_tf32(kv.w) };
        uint4 vt = { f32_tf32(vv.x), f32_tf32(vv.y), f32_tf32(vv.z), f32_tf32(vv.w) };
        reinterpret_cast<uint4*>(g_kt)[dst] = kt;
        reinterpret_cast<uint4*>(g_vt)[dst] = vt;
    }
}

// ---------------- shared tf32 GEMM mainloop: C(128x128)=A(128xK)*B(128xK)^T
// 8 warps (2m x 4n), warp tile 64x32, K-step 32, cp.async double buffer.
constexpr int GL_STR = 36;
constexpr int GL_BUF = 128 * GL_STR;
constexpr int GEMM_SMEM_BYTES = 4 * GL_BUF * 4;   // 73728

__device__ __forceinline__ void gemm_fill(
    uint32_t* As, uint32_t* Bs,
    const uint32_t* __restrict__ A, const uint32_t* __restrict__ B,
    int K, int k0, int tid)
{
#pragma unroll
    for (int i = 0; i < 4; i++) {
        int c = tid + 256 * i, row = c >> 3, c4 = (c & 7) * 4;
        cp16(smaddr(As + row * GL_STR + c4), A + (size_t)row * K + k0 + c4);
        cp16(smaddr(Bs + row * GL_STR + c4), B + (size_t)row * K + k0 + c4);
    }
}

__device__ __forceinline__ void gemm_main(
    const uint32_t* __restrict__ A, const uint32_t* __restrict__ B,
    int K, uint32_t* sm, float (&acc)[4][4][4])
{
    uint32_t* As = sm;
    uint32_t* Bs = sm + 2 * GL_BUF;
    const int tid = threadIdx.x, lane = tid & 31, wid = tid >> 5;
    const int g = lane >> 2, q = lane & 3, wm = wid >> 2, wn = wid & 3;

#pragma unroll
    for (int mt = 0; mt < 4; mt++)
#pragma unroll
        for (int nt = 0; nt < 4; nt++)
#pragma unroll
            for (int c = 0; c < 4; c++) acc[mt][nt][c] = 0.f;

    const int nk = K / 32;
    gemm_fill(As, Bs, A, B, K, 0, tid);
    CP_COMMIT();
    for (int kt = 0; kt < nk; kt++) {
        const int cur = kt & 1;
        CP_WAIT0();
        __syncthreads();
        if (kt + 1 < nk) {
            gemm_fill(As + (cur ^ 1) * GL_BUF, Bs + (cur ^ 1) * GL_BUF,
                      A, B, K, (kt + 1) * 32, tid);
            CP_COMMIT();
        }
        const uint32_t* a_s = As + cur * GL_BUF;
        const uint32_t* b_s = Bs + cur * GL_BUF;
#pragma unroll
        for (int kc = 0; kc < 4; kc++) {
            const int kk = kc * 8 + q;
            uint32_t af[4][4], bf[4][2];
#pragma unroll
            for (int mt = 0; mt < 4; mt++) {
                int r = wm * 64 + mt * 16 + g;
                af[mt][0] = a_s[r * GL_STR + kk];
                af[mt][1] = a_s[(r + 8) * GL_STR + kk];
                af[mt][2] = a_s[r * GL_STR + kk + 4];
                af[mt][3] = a_s[(r + 8) * GL_STR + kk + 4];
            }
#pragma unroll
            for (int nt = 0; nt < 4; nt++) {
                int n = wn * 32 + nt * 8 + g;
                bf[nt][0] = b_s[n * GL_STR + kk];
                bf[nt][1] = b_s[n * GL_STR + kk + 4];
            }
#pragma unroll
            for (int mt = 0; mt < 4; mt++)
#pragma unroll
                for (int nt = 0; nt < 4; nt++)
                    mma8(acc[mt][nt], af[mt], bf[nt]);
        }
    }
}

// ---------------- QKV projection + bias + scatter --------------------------
__global__ void __launch_bounds__(256, 2)
k_qkv_mma(const float* __restrict__ bias,
          float* __restrict__ kout, float* __restrict__ vout)
{
    extern __shared__ uint32_t smu[];
    float acc[4][4][4];
    gemm_main(g_xt + (size_t)blockIdx.y * 128 * D_,
              g_wq + (size_t)blockIdx.x * 128 * D_, D_, smu, acc);
    const int lane = threadIdx.x & 31, wid = threadIdx.x >> 5;
    const int g = lane >> 2, q = lane & 3, wm = wid >> 2, wn = wid & 3;
#pragma unroll
    for (int mt = 0; mt < 4; mt++)
#pragma unroll
        for (int c = 0; c < 4; c++) {
            int m = blockIdx.y * 128 + wm * 64 + mt * 16 + g + ((c >= 2) ? 8 : 0);
            int b = m >> 11, s = m & (S_ - 1);
#pragma unroll
            for (int nt = 0; nt < 4; nt++) {
                int n = blockIdx.x * 128 + wn * 32 + nt * 8 + 2 * q + (c & 1);
                float v = acc[mt][nt][c] + bias[n];
                int sec = n >> 11, d0 = n & (D_ - 1);
                int h = d0 >> 7, hd = d0 & 127;
                if (sec == 0) {
                    g_q[(((size_t)(b * H_ + h)) * S_ + s) * HD_ + hd] = f32_tf32(v * SCALE_);
                } else {
                    size_t idx = (((size_t)(b * H_ + h)) * SKV_ + (PAST_ + s)) * HD_ + hd;
                    if (sec == 1) { kout[idx] = v; g_kt[idx] = f32_tf32(v); }
                    else          { vout[idx] = v; g_vt[idx] = f32_tf32(v); }
                }
            }
        }
}

// ---------------- output projection + bias ---------------------------------
__global__ void __launch_bounds__(256, 2)
k_out_mma(const float* __restrict__ bias, float* __restrict__ out)
{
    extern __shared__ uint32_t smu[];
    float acc[4][4][4];
    gemm_main(g_attn + (size_t)blockIdx.y * 128 * D_,
              g_wo   + (size_t)blockIdx.x * 128 * D_, D_, smu, acc);
    const int lane = threadIdx.x & 31, wid = threadIdx.x >> 5;
    const int g = lane >> 2, q = lane & 3, wm = wid >> 2, wn = wid & 3;
#pragma unroll
    for (int mt = 0; mt < 4; mt++)
#pragma unroll
        for (int half = 0; half < 2; half++) {
            int m = blockIdx.y * 128 + wm * 64 + mt * 16 + g + 8 * half;
#pragma unroll
            for (int nt = 0; nt < 4; nt++) {
                int n = blockIdx.x * 128 + wn * 32 + nt * 8 + 2 * q;
                float2 o2 = { acc[mt][nt][2 * half]     + bias[n],
                              acc[mt][nt][2 * half + 1] + bias[n + 1] };
                *reinterpret_cast<float2*>(out + (size_t)m * D_ + n) = o2;
            }
        }
}

// ---------------- fused flash attention (tf32 mma, online softmax) ---------
// Block = 128 q rows x one z. KV tiles of 64. 8 warps, each owns 16-row strip.
constexpr int FK_STR = 132;
constexpr int FV_STR = 136;
constexpr int F_KS   = 0;
constexpr int F_VS   = 2 * 64 * FK_STR;
constexpr int F_QS   = F_VS + 64 * FV_STR;
constexpr int FLASH_SMEM_BYTES = (F_QS + 128 * FK_STR) * 4;   // 169984

__global__ void __launch_bounds__(256, 1)
k_flash_mma()
{
    extern __shared__ uint32_t smu[];
    uint32_t* KS = smu + F_KS;
    uint32_t* VS = smu + F_VS;
    uint32_t* QS = smu + F_QS;

    const int z = blockIdx.y, tid = threadIdx.x;
    const int lane = tid & 31, wid = tid >> 5;
    const int g = lane >> 2, q = lane & 3;

    const uint32_t* qg = g_q  + (size_t)z * S_   * HD_ + (size_t)blockIdx.x * 128 * HD_;
    const uint32_t* kz = g_kt + (size_t)z * SKV_ * HD_;
    const uint32_t* vz = g_vt + (size_t)z * SKV_ * HD_;

#pragma unroll
    for (int i = 0; i < 16; i++) {
        int c = tid + 256 * i, row = c >> 5, c4 = (c & 31) * 4;
        cp16(smaddr(QS + row * FK_STR + c4), qg + (size_t)row * HD_ + c4);
    }
    CP_COMMIT();
#pragma unroll
    for (int i = 0; i < 8; i++) {
        int c = tid + 256 * i, row = c >> 5, c4 = (c & 31) * 4;
        cp16(smaddr(KS + row * FK_STR + c4), kz + (size_t)row * HD_ + c4);
    }
    CP_COMMIT();
    CP_WAIT0();
    __syncthreads();

    uint32_t qa[16][4];
    {
        const int r = wid * 16 + g;
#pragma unroll
        for (int kc = 0; kc < 16; kc++) {
            int kk = kc * 8 + q;
            qa[kc][0] = QS[r * FK_STR + kk];
            qa[kc][1] = QS[(r + 8) * FK_STR + kk];
            qa[kc][2] = QS[r * FK_STR + kk + 4];
            qa[kc][3] = QS[(r + 8) * FK_STR + kk + 4];
        }
    }

    float o[16][4];
#pragma unroll
    for (int nt = 0; nt < 16; nt++)
#pragma unroll
        for (int c = 0; c < 4; c++) o[nt][c] = 0.f;
    float mrow[2] = { -3.0e38f, -3.0e38f };
    float lrow[2] = { 0.f, 0.f };

    const int NT = SKV_ / 64;
    for (int t = 0; t < NT; t++) {
        const int cur = t & 1;
        if (t > 0) { CP_WAIT0(); __syncthreads(); }
        // issue V(t)
#pragma unroll
        for (int i = 0; i < 8; i++) {
            int c = tid + 256 * i, row = c >> 5, c4 = (c & 31) * 4;
            cp16(smaddr(VS + row * FV_STR + c4), vz + (size_t)(t * 64 + row) * HD_ + c4);
        }
        CP_COMMIT();

        // S = Q @ K^T  (16 rows x 64 kv per warp)
        const uint32_t* ks = KS + cur * 64 * FK_STR;
        float s[8][4];
#pragma unroll
        for (int nt = 0; nt < 8; nt++)
#pragma unroll
            for (int c = 0; c < 4; c++) s[nt][c] = 0.f;
#pragma unroll
        for (int kc = 0; kc < 16; kc++) {
            const int kk = kc * 8 + q;
#pragma unroll
            for (int nt = 0; nt < 8; nt++) {
                uint32_t bf[2];
                bf[0] = ks[(nt * 8 + g) * FK_STR + kk];
                bf[1] = ks[(nt * 8 + g) * FK_STR + kk + 4];
                mma8(s[nt], qa[kc], bf);
            }
        }

        // online softmax (rows g and g+8 per thread)
#pragma unroll
        for (int hh = 0; hh < 2; hh++) {
            float mx = -3.0e38f;
#pragma unroll
            for (int nt = 0; nt < 8; nt++)
                mx = fmaxf(mx, fmaxf(s[nt][2 * hh], s[nt][2 * hh + 1]));
            mx = fmaxf(mx, __shfl_xor_sync(0xffffffffu, mx, 1));
            mx = fmaxf(mx, __shfl_xor_sync(0xffffffffu, mx, 2));
            float M = fmaxf(mrow[hh], mx);
            float corr = __expf(mrow[hh] - M);
            mrow[hh] = M;
            float sum = 0.f;
#pragma unroll
            for (int nt = 0; nt < 8; nt++) {
                s[nt][2 * hh]     = __expf(s[nt][2 * hh]     - M);
                s[nt][2 * hh + 1] = __expf(s[nt][2 * hh + 1] - M);
                sum += s[nt][2 * hh] + s[nt][2 * hh + 1];
            }
            sum += __shfl_xor_sync(0xffffffffu, sum, 1);
            sum += __shfl_xor_sync(0xffffffffu, sum, 2);
            lrow[hh] = lrow[hh] * corr + sum;
#pragma unroll
            for (int nt = 0; nt < 16; nt++) {
                o[nt][2 * hh]     *= corr;
                o[nt][2 * hh + 1] *= corr;
            }
        }

        CP_WAIT0();       // V(t) landed
        __syncthreads();

        // O += P @ V ; P remapped C-frag -> A-frag via quad shuffles
        const int srcA = (lane & ~3) | (q >> 1);
        const int srcC = srcA + 2;
        const bool e = (q & 1);
#pragma unroll
        for (int kc = 0; kc < 8; kc++) {
            uint32_t p0 = f32_tf32(s[kc][0]);
            uint32_t p1 = f32_tf32(s[kc][1]);
            uint32_t p2 = f32_tf32(s[kc][2]);
            uint32_t p3 = f32_tf32(s[kc][3]);
            uint32_t v00 = __shfl_sync(0xffffffffu, p0, srcA);
            uint32_t v01 = __shfl_sync(0xffffffffu, p1, srcA);
            uint32_t v10 = __shfl_sync(0xffffffffu, p0, srcC);
            uint32_t v11 = __shfl_sync(0xffffffffu, p1, srcC);
            uint32_t v20 = __shfl_sync(0xffffffffu, p2, srcA);
            uint32_t v21 = __shfl_sync(0xffffffffu, p3, srcA);
            uint32_t v30 = __shfl_sync(0xffffffffu, p2, srcC);
            uint32_t v31 = __shfl_sync(0xffffffffu, p3, srcC);
            uint32_t af[4];
            af[0] = e ? v01 : v00;
            af[1] = e ? v21 : v20;
            af[2] = e ? v11 : v10;
            af[3] = e ? v31 : v30;
            const int k0 = kc * 8 + q;
#pragma unroll
            for (int nt = 0; nt < 16; nt++) {
                uint32_t bf[2];
                bf[0] = VS[k0 * FV_STR + nt * 8 + g];
                bf[1] = VS[(k0 + 4) * FV_STR + nt * 8 + g];
                mma8(o[nt], af, bf);
            }
        }

        // prefetch K(t+1)
        if (t + 1 < NT) {
#pragma unroll
            for (int i = 0; i < 8; i++) {
                int c = tid + 256 * i, row = c >> 5, c4 = (c & 31) * 4;
                cp16(smaddr(KS + (cur ^ 1) * 64 * FK_STR + row * FK_STR + c4),
                     kz + (size_t)((t + 1) * 64 + row) * HD_ + c4);
            }
            CP_COMMIT();
        }
    }

    // epilogue: normalize, store tf32 to g_attn[b, s, h*128 + hd]
    const int b = z >> 4, h = z & 15;
#pragma unroll
    for (int hh = 0; hh < 2; hh++) {
        float inv = 1.0f / lrow[hh];
        int srow = blockIdx.x * 128 + wid * 16 + g + 8 * hh;
        size_t base = ((size_t)(b * S_ + srow)) * D_ + h * 128;
#pragma unroll
        for (int nt = 0; nt < 16; nt++) {
            uint2 o2 = { f32_tf32(o[nt][2 * hh] * inv),
                         f32_tf32(o[nt][2 * hh + 1] * inv) };
            *reinterpret_cast<uint2*>(g_attn + base + nt * 8 + 2 * q) = o2;
        }
    }
}

// ---------------------------------------------------------------------------
// Launcher: d_out = [ out | k | v ]
// ---------------------------------------------------------------------------
extern "C" void kernel_launch(void* const* d_in, const int* in_sizes, int n_in,
                              void* d_out, int out_size)
{
    const float* x      = (const float*)d_in[0];
    const float* past_k = (const float*)d_in[1];
    const float* past_v = (const float*)d_in[2];
    const float* qkv_w  = (const float*)d_in[3];
    const float* qkv_b  = (const float*)d_in[4];
    const float* out_w  = (const float*)d_in[5];
    const float* out_b  = (const float*)d_in[6];

    float* out  = (float*)d_out;
    float* kout = out  + (size_t)B_ * S_ * D_;
    float* vout = kout + (size_t)B_ * H_ * SKV_ * HD_;

    cudaFuncSetAttribute(k_flash_mma, cudaFuncAttributeMaxDynamicSharedMemorySize,
                         FLASH_SMEM_BYTES);
    cudaFuncSetAttribute(k_qkv_mma, cudaFuncAttributeMaxDynamicSharedMemorySize,
                         GEMM_SMEM_BYTES);
    cudaFuncSetAttribute(k_out_mma, cudaFuncAttributeMaxDynamicSharedMemorySize,
                         GEMM_SMEM_BYTES);

    k_cvt<<<2048, 256>>>((const float4*)x,     0, M_X * D_ / 4);
    k_cvt<<<2048, 256>>>((const float4*)qkv_w, 1, TD_ * D_ / 4);
    k_cvt<<<2048, 256>>>((const float4*)out_w, 2, D_ * D_ / 4);
    k_copy_past<<<8192, 256>>>((const float4*)past_k, (const float4*)past_v,
                               (float4*)kout, (float4*)vout);
    k_qkv_mma<<<dim3(TD_ / 128, M_X / 128), 256, GEMM_SMEM_BYTES>>>(qkv_b, kout, vout);
    k_flash_mma<<<dim3(S_ / 128, B_ * H_), 256, FLASH_SMEM_BYTES>>>();
    k_out_mma<<<dim3(D_ / 128, M_X / 128), 256, GEMM_SMEM_BYTES>>>(out_b, out);
}

// round 7
// speedup vs baseline: 3.8421x; 1.0650x over previous
#include <cuda_runtime.h>
#include <math.h>
#include <stdint.h>

constexpr int B_    = 2;
constexpr int S_    = 2048;
constexpr int D_    = 2048;
constexpr int H_    = 16;
constexpr int HD_   = 128;
constexpr int PAST_ = 2048;
constexpr int SKV_  = 4096;
constexpr int M_X   = B_ * S_;     // 4096
constexpr int TD_   = 3 * D_;      // 6144
constexpr float SCALE_ = 0.08838834764831845f;

// tf32 operand buffers. All K-contiguous operands are stored PERMUTED:
// within each 8-element K-group, order is [0,4,1,5,2,6,3,7] so that a
// quad-lane's mma fragment pair (k, k+4) is one contiguous 8-byte load.
__device__ uint32_t g_xt  [(size_t)M_X * D_];              // permuted
__device__ uint32_t g_wq  [(size_t)TD_ * D_];              // permuted
__device__ uint32_t g_wo  [(size_t)D_ * D_];               // permuted
__device__ uint32_t g_q   [(size_t)B_ * H_ * S_ * HD_];    // q*SCALE, permuted
__device__ uint32_t g_kt  [(size_t)B_ * H_ * SKV_ * HD_];  // permuted
__device__ uint32_t g_vt  [(size_t)B_ * H_ * SKV_ * HD_];  // RAW (N-operand)
__device__ uint32_t g_attn[(size_t)M_X * D_];              // permuted

__device__ __forceinline__ uint32_t f32_tf32(float x) {
    uint32_t u; asm("cvt.rna.tf32.f32 %0, %1;" : "=r"(u) : "f"(x)); return u;
}
__device__ __forceinline__ int permi(int e) {   // position of orig element e
    return (e < 4) ? 2 * e : 2 * (e - 4) + 1;
}
__device__ __forceinline__ void mma8(float* d, const uint32_t* a, const uint32_t* b) {
    asm volatile(
        "mma.sync.aligned.m16n8k8.row.col.f32.tf32.tf32.f32 "
        "{%0,%1,%2,%3},{%4,%5,%6,%7},{%8,%9},{%0,%1,%2,%3};"
        : "+f"(d[0]), "+f"(d[1]), "+f"(d[2]), "+f"(d[3])
        : "r"(a[0]), "r"(a[1]), "r"(a[2]), "r"(a[3]), "r"(b[0]), "r"(b[1]));
}
__device__ __forceinline__ void cp16(uint32_t dst, const void* src) {
    asm volatile("cp.async.cg.shared.global [%0], [%1], 16;" :: "r"(dst), "l"(src));
}
#define CP_COMMIT() asm volatile("cp.async.commit_group;")
#define CP_WAIT0()  asm volatile("cp.async.wait_group 0;")
#define CP_WAIT1()  asm volatile("cp.async.wait_group 1;")
__device__ __forceinline__ uint32_t smaddr(const void* p) {
    return (uint32_t)__cvta_generic_to_shared(p);
}

// ---------------- convert f32 -> tf32, permuted group write ----------------
// processes 8 elements (one K-group) per thread: out chunk0 = {e0,e4,e1,e5},
// chunk1 = {e2,e6,e3,e7}.
__global__ void __launch_bounds__(256)
k_cvt(const float4* __restrict__ src, int which, int n8)
{
    uint4* dst = (which == 0) ? reinterpret_cast<uint4*>(g_xt)
               : (which == 1) ? reinterpret_cast<uint4*>(g_wq)
                              : reinterpret_cast<uint4*>(g_wo);
    for (int i = blockIdx.x * 256 + threadIdx.x; i < n8; i += gridDim.x * 256) {
        float4 a = src[2 * i], b = src[2 * i + 1];
        uint4 o0 = { f32_tf32(a.x), f32_tf32(b.x), f32_tf32(a.y), f32_tf32(b.y) };
        uint4 o1 = { f32_tf32(a.z), f32_tf32(b.z), f32_tf32(a.w), f32_tf32(b.w) };
        dst[2 * i]     = o0;
        dst[2 * i + 1] = o1;
    }
}

// ---------------- past copy: raw f32 outputs + tf32 mirrors ----------------
// 8 elements per thread. g_kt permuted, g_vt raw.
__global__ void __launch_bounds__(256)
k_copy_past(const float4* __restrict__ pk, const float4* __restrict__ pv,
            float4* __restrict__ ko, float4* __restrict__ vo)
{
    size_t i = (size_t)blockIdx.x * 256 + threadIdx.x;
    constexpr size_t n8     = (size_t)B_ * H_ * PAST_ * HD_ / 8;
    constexpr size_t chunk  = (size_t)PAST_ * HD_ / 8;
    constexpr size_t dchunk = (size_t)SKV_  * HD_ / 8;
    if (i < n8) {
        size_t bh = i / chunk, rem = i - bh * chunk, dst = bh * dchunk + rem;
        float4 ka = pk[2 * i], kb = pk[2 * i + 1];
        float4 va = pv[2 * i], vb = pv[2 * i + 1];
        ko[2 * dst] = ka; ko[2 * dst + 1] = kb;
        vo[2 * dst] = va; vo[2 * dst + 1] = vb;
        // g_kt permuted
        uint4 k0 = { f32_tf32(ka.x), f32_tf32(kb.x), f32_tf32(ka.y), f32_tf32(kb.y) };
        uint4 k1 = { f32_tf32(ka.z), f32_tf32(kb.z), f32_tf32(ka.w), f32_tf32(kb.w) };
        reinterpret_cast<uint4*>(g_kt)[2 * dst]     = k0;
        reinterpret_cast<uint4*>(g_kt)[2 * dst + 1] = k1;
        // g_vt raw
        uint4 v0 = { f32_tf32(va.x), f32_tf32(va.y), f32_tf32(va.z), f32_tf32(va.w) };
        uint4 v1 = { f32_tf32(vb.x), f32_tf32(vb.y), f32_tf32(vb.z), f32_tf32(vb.w) };
        reinterpret_cast<uint4*>(g_vt)[2 * dst]     = v0;
        reinterpret_cast<uint4*>(g_vt)[2 * dst + 1] = v1;
    }
}

// ---------------- shared tf32 GEMM mainloop --------------------------------
// C(128x128)=A(128xK)*B(128xK)^T, operands permuted -> all frag loads LDS.64.
// 8 warps (2m x 4n), warp tile 64x32, K-step 32, cp.async double buffer.
// Row stride 40 u32 (mod 32 == 8) -> conflict-free LDS.64.
constexpr int GL_STR = 40;
constexpr int GL_BUF = 128 * GL_STR;              // 5120
constexpr int GEMM_SMEM_BYTES = 4 * GL_BUF * 4;   // 81920

__device__ __forceinline__ void gemm_fill(
    uint32_t* As, uint32_t* Bs,
    const uint32_t* __restrict__ A, const uint32_t* __restrict__ B,
    int K, int k0, int tid)
{
#pragma unroll
    for (int i = 0; i < 4; i++) {
        int c = tid + 256 * i, row = c >> 3, c4 = (c & 7) * 4;
        cp16(smaddr(As + row * GL_STR + c4), A + (size_t)row * K + k0 + c4);
        cp16(smaddr(Bs + row * GL_STR + c4), B + (size_t)row * K + k0 + c4);
    }
}

__device__ __forceinline__ void gemm_main(
    const uint32_t* __restrict__ A, const uint32_t* __restrict__ B,
    int K, uint32_t* sm, float (&acc)[4][4][4])
{
    uint32_t* As = sm;
    uint32_t* Bs = sm + 2 * GL_BUF;
    const int tid = threadIdx.x, lane = tid & 31, wid = tid >> 5;
    const int g = lane >> 2, q = lane & 3, wm = wid >> 2, wn = wid & 3;

#pragma unroll
    for (int mt = 0; mt < 4; mt++)
#pragma unroll
        for (int nt = 0; nt < 4; nt++)
#pragma unroll
            for (int c = 0; c < 4; c++) acc[mt][nt][c] = 0.f;

    const int nk = K / 32;
    gemm_fill(As, Bs, A, B, K, 0, tid);
    CP_COMMIT();
    for (int kt = 0; kt < nk; kt++) {
        const int cur = kt & 1;
        CP_WAIT0();
        __syncthreads();
        if (kt + 1 < nk) {
            gemm_fill(As + (cur ^ 1) * GL_BUF, Bs + (cur ^ 1) * GL_BUF,
                      A, B, K, (kt + 1) * 32, tid);
            CP_COMMIT();
        }
        const uint32_t* a_s = As + cur * GL_BUF;
        const uint32_t* b_s = Bs + cur * GL_BUF;
#pragma unroll
        for (int kc = 0; kc < 4; kc++) {
            const int col = kc * 8 + 2 * q;     // permuted: holds orig (k, k+4)
            uint32_t af[4][4], bf[4][2];
#pragma unroll
            for (int mt = 0; mt < 4; mt++) {
                int r = wm * 64 + mt * 16 + g;
                uint2 lo = *reinterpret_cast<const uint2*>(a_s + r * GL_STR + col);
                uint2 hi = *reinterpret_cast<const uint2*>(a_s + (r + 8) * GL_STR + col);
                af[mt][0] = lo.x; af[mt][1] = hi.x; af[mt][2] = lo.y; af[mt][3] = hi.y;
            }
#pragma unroll
            for (int nt = 0; nt < 4; nt++) {
                int n = wn * 32 + nt * 8 + g;
                uint2 bb = *reinterpret_cast<const uint2*>(b_s + n * GL_STR + col);
                bf[nt][0] = bb.x; bf[nt][1] = bb.y;
            }
#pragma unroll
            for (int mt = 0; mt < 4; mt++)
#pragma unroll
                for (int nt = 0; nt < 4; nt++)
                    mma8(acc[mt][nt], af[mt], bf[nt]);
        }
    }
}

// ---------------- QKV projection + bias + scatter --------------------------
__global__ void __launch_bounds__(256, 2)
k_qkv_mma(const float* __restrict__ bias,
          float* __restrict__ kout, float* __restrict__ vout)
{
    extern __shared__ uint32_t smu[];
    float acc[4][4][4];
    gemm_main(g_xt + (size_t)blockIdx.y * 128 * D_,
              g_wq + (size_t)blockIdx.x * 128 * D_, D_, smu, acc);
    const int lane = threadIdx.x & 31, wid = threadIdx.x >> 5;
    const int g = lane >> 2, q = lane & 3, wm = wid >> 2, wn = wid & 3;
#pragma unroll
    for (int mt = 0; mt < 4; mt++)
#pragma unroll
        for (int c = 0; c < 4; c++) {
            int m = blockIdx.y * 128 + wm * 64 + mt * 16 + g + ((c >= 2) ? 8 : 0);
            int b = m >> 11, s = m & (S_ - 1);
#pragma unroll
            for (int nt = 0; nt < 4; nt++) {
                int n = blockIdx.x * 128 + wn * 32 + nt * 8 + 2 * q + (c & 1);
                float v = acc[mt][nt][c] + bias[n];
                int sec = n >> 11, d0 = n & (D_ - 1);
                int h = d0 >> 7, hd = d0 & 127;
                int hdp = (hd & ~7) + permi(hd & 7);     // permuted hd
                if (sec == 0) {
                    g_q[(((size_t)(b * H_ + h)) * S_ + s) * HD_ + hdp] =
                        f32_tf32(v * SCALE_);
                } else {
                    size_t base = (((size_t)(b * H_ + h)) * SKV_ + (PAST_ + s)) * HD_;
                    if (sec == 1) { kout[base + hd] = v; g_kt[base + hdp] = f32_tf32(v); }
                    else          { vout[base + hd] = v; g_vt[base + hd]  = f32_tf32(v); }
                }
            }
        }
}

// ---------------- output projection + bias ---------------------------------
__global__ void __launch_bounds__(256, 2)
k_out_mma(const float* __restrict__ bias, float* __restrict__ out)
{
    extern __shared__ uint32_t smu[];
    float acc[4][4][4];
    gemm_main(g_attn + (size_t)blockIdx.y * 128 * D_,
              g_wo   + (size_t)blockIdx.x * 128 * D_, D_, smu, acc);
    const int lane = threadIdx.x & 31, wid = threadIdx.x >> 5;
    const int g = lane >> 2, q = lane & 3, wm = wid >> 2, wn = wid & 3;
#pragma unroll
    for (int mt = 0; mt < 4; mt++)
#pragma unroll
        for (int half = 0; half < 2; half++) {
            int m = blockIdx.y * 128 + wm * 64 + mt * 16 + g + 8 * half;
#pragma unroll
            for (int nt = 0; nt < 4; nt++) {
                int n = blockIdx.x * 128 + wn * 32 + nt * 8 + 2 * q;
                float2 o2 = { acc[mt][nt][2 * half]     + bias[n],
                              acc[mt][nt][2 * half + 1] + bias[n + 1] };
                *reinterpret_cast<float2*>(out + (size_t)m * D_ + n) = o2;
            }
        }
}

// ---------------- fused flash attention (tf32 mma, online softmax) ---------
// Block = 128 q rows x one z. KV tiles of 64. 8 warps, each owns 16-row strip.
// K/Q permuted -> LDS.64 frag loads; V raw. K(t+1) prefetch overlapped with
// softmax+PV via wait_group 1.
constexpr int FK_STR = 136;      // mod 32 == 8 -> conflict-free LDS.64
constexpr int FV_STR = 136;
constexpr int F_KS   = 0;
constexpr int F_VS   = 2 * 64 * FK_STR;               // 17408
constexpr int F_QS   = F_VS + 64 * FV_STR;            // 26112
constexpr int FLASH_SMEM_BYTES = (F_QS + 128 * FK_STR) * 4;   // 174080

__global__ void __launch_bounds__(256, 1)
k_flash_mma()
{
    extern __shared__ uint32_t smu[];
    uint32_t* KS = smu + F_KS;
    uint32_t* VS = smu + F_VS;
    uint32_t* QS = smu + F_QS;

    const int z = blockIdx.y, tid = threadIdx.x;
    const int lane = tid & 31, wid = tid >> 5;
    const int g = lane >> 2, q = lane & 3;

    const uint32_t* qg = g_q  + (size_t)z * S_   * HD_ + (size_t)blockIdx.x * 128 * HD_;
    const uint32_t* kz = g_kt + (size_t)z * SKV_ * HD_;
    const uint32_t* vz = g_vt + (size_t)z * SKV_ * HD_;

#pragma unroll
    for (int i = 0; i < 16; i++) {
        int c = tid + 256 * i, row = c >> 5, c4 = (c & 31) * 4;
        cp16(smaddr(QS + row * FK_STR + c4), qg + (size_t)row * HD_ + c4);
    }
#pragma unroll
    for (int i = 0; i < 8; i++) {
        int c = tid + 256 * i, row = c >> 5, c4 = (c & 31) * 4;
        cp16(smaddr(KS + row * FK_STR + c4), kz + (size_t)row * HD_ + c4);
    }
    CP_COMMIT();
    CP_WAIT0();
    __syncthreads();

    // Q fragments (permuted layout -> LDS.64 pairs)
    uint32_t qa[16][4];
    {
        const int r = wid * 16 + g;
#pragma unroll
        for (int kc = 0; kc < 16; kc++) {
            int col = kc * 8 + 2 * q;
            uint2 lo = *reinterpret_cast<const uint2*>(QS + r * FK_STR + col);
            uint2 hi = *reinterpret_cast<const uint2*>(QS + (r + 8) * FK_STR + col);
            qa[kc][0] = lo.x; qa[kc][1] = hi.x; qa[kc][2] = lo.y; qa[kc][3] = hi.y;
        }
    }

    float o[16][4];
#pragma unroll
    for (int nt = 0; nt < 16; nt++)
#pragma unroll
        for (int c = 0; c < 4; c++) o[nt][c] = 0.f;
    float mrow[2] = { -3.0e38f, -3.0e38f };
    float lrow[2] = { 0.f, 0.f };

    const int NT = SKV_ / 64;
    for (int t = 0; t < NT; t++) {
        const int cur = t & 1;
        if (t > 0) { CP_WAIT0(); __syncthreads(); }   // K(t) landed, VS free

        // issue V(t) [group], then K(t+1) [group] -- both overlap QK+softmax
#pragma unroll
        for (int i = 0; i < 8; i++) {
            int c = tid + 256 * i, row = c >> 5, c4 = (c & 31) * 4;
            cp16(smaddr(VS + row * FV_STR + c4), vz + (size_t)(t * 64 + row) * HD_ + c4);
        }
        CP_COMMIT();
        if (t + 1 < NT) {
#pragma unroll
            for (int i = 0; i < 8; i++) {
                int c = tid + 256 * i, row = c >> 5, c4 = (c & 31) * 4;
                cp16(smaddr(KS + (cur ^ 1) * 64 * FK_STR + row * FK_STR + c4),
                     kz + (size_t)((t + 1) * 64 + row) * HD_ + c4);
            }
            CP_COMMIT();
        }

        // S = Q @ K^T  (16 rows x 64 kv per warp)
        const uint32_t* ks = KS + cur * 64 * FK_STR;
        float s[8][4];
#pragma unroll
        for (int nt = 0; nt < 8; nt++)
#pragma unroll
            for (int c = 0; c < 4; c++) s[nt][c] = 0.f;
#pragma unroll
        for (int kc = 0; kc < 16; kc++) {
            const int col = kc * 8 + 2 * q;
#pragma unroll
            for (int nt = 0; nt < 8; nt++) {
                uint2 bb = *reinterpret_cast<const uint2*>(
                    ks + (nt * 8 + g) * FK_STR + col);
                uint32_t bf[2] = { bb.x, bb.y };
                mma8(s[nt], qa[kc], bf);
            }
        }

        // online softmax (rows g and g+8 per thread)
#pragma unroll
        for (int hh = 0; hh < 2; hh++) {
            float mx = -3.0e38f;
#pragma unroll
            for (int nt = 0; nt < 8; nt++)
                mx = fmaxf(mx, fmaxf(s[nt][2 * hh], s[nt][2 * hh + 1]));
            mx = fmaxf(mx, __shfl_xor_sync(0xffffffffu, mx, 1));
            mx = fmaxf(mx, __shfl_xor_sync(0xffffffffu, mx, 2));
            float M = fmaxf(mrow[hh], mx);
            float corr = __expf(mrow[hh] - M);
            mrow[hh] = M;
            float sum = 0.f;
#pragma unroll
            for (int nt = 0; nt < 8; nt++) {
                s[nt][2 * hh]     = __expf(s[nt][2 * hh]     - M);
                s[nt][2 * hh + 1] = __expf(s[nt][2 * hh + 1] - M);
                sum += s[nt][2 * hh] + s[nt][2 * hh + 1];
            }
            sum += __shfl_xor_sync(0xffffffffu, sum, 1);
            sum += __shfl_xor_sync(0xffffffffu, sum, 2);
            lrow[hh] = lrow[hh] * corr + sum;
#pragma unroll
            for (int nt = 0; nt < 16; nt++) {
                o[nt][2 * hh]     *= corr;
                o[nt][2 * hh + 1] *= corr;
            }
        }

        // V(t) ready (leave K(t+1) in flight)
        if (t + 1 < NT) { CP_WAIT1(); } else { CP_WAIT0(); }
        __syncthreads();

        // O += P @ V ; P remapped C-frag -> A-frag via quad shuffles
        const int srcA = (lane & ~3) | (q >> 1);
        const int srcC = srcA + 2;
        const bool e = (q & 1);
#pragma unroll
        for (int kc = 0; kc < 8; kc++) {
            uint32_t p0 = f32_tf32(s[kc][0]);
            uint32_t p1 = f32_tf32(s[kc][1]);
            uint32_t p2 = f32_tf32(s[kc][2]);
            uint32_t p3 = f32_tf32(s[kc][3]);
            uint32_t v00 = __shfl_sync(0xffffffffu, p0, srcA);
            uint32_t v01 = __shfl_sync(0xffffffffu, p1, srcA);
            uint32_t v10 = __shfl_sync(0xffffffffu, p0, srcC);
            uint32_t v11 = __shfl_sync(0xffffffffu, p1, srcC);
            uint32_t v20 = __shfl_sync(0xffffffffu, p2, srcA);
            uint32_t v21 = __shfl_sync(0xffffffffu, p3, srcA);
            uint32_t v30 = __shfl_sync(0xffffffffu, p2, srcC);
            uint32_t v31 = __shfl_sync(0xffffffffu, p3, srcC);
            uint32_t af[4];
            af[0] = e ? v01 : v00;
            af[1] = e ? v21 : v20;
            af[2] = e ? v11 : v10;
            af[3] = e ? v31 : v30;
            const int k0 = kc * 8 + q;
#pragma unroll
            for (int nt = 0; nt < 16; nt++) {
                uint32_t bf[2];
                bf[0] = VS[k0 * FV_STR + nt * 8 + g];
                bf[1] = VS[(k0 + 4) * FV_STR + nt * 8 + g];
                mma8(o[nt], af, bf);
            }
        }
    }

    // epilogue: normalize, store PERMUTED tf32 to g_attn[b, s, h*128 + hd]
    const int b = z >> 4, h = z & 15;
#pragma unroll
    for (int hh = 0; hh < 2; hh++) {
        float inv = 1.0f / lrow[hh];
        int srow = blockIdx.x * 128 + wid * 16 + g + 8 * hh;
        size_t base = ((size_t)(b * S_ + srow)) * D_ + h * 128;
#pragma unroll
        for (int nt = 0; nt < 16; nt++) {
            int e0 = 2 * q, e1 = 2 * q + 1;
            g_attn[base + nt * 8 + permi(e0)] = f32_tf32(o[nt][2 * hh] * inv);
            g_attn[base + nt * 8 + permi(e1)] = f32_tf32(o[nt][2 * hh + 1] * inv);
        }
    }
}

// ---------------------------------------------------------------------------
// Launcher: d_out = [ out | k | v ]
// ---------------------------------------------------------------------------
extern "C" void kernel_launch(void* const* d_in, const int* in_sizes, int n_in,
                              void* d_out, int out_size)
{
    const float* x      = (const float*)d_in[0];
    const float* past_k = (const float*)d_in[1];
    const float* past_v = (const float*)d_in[2];
    const float* qkv_w  = (const float*)d_in[3];
    const float* qkv_b  = (const float*)d_in[4];
    const float* out_w  = (const float*)d_in[5];
    const float* out_b  = (const float*)d_in[6];

    float* out  = (float*)d_out;
    float* kout = out  + (size_t)B_ * S_ * D_;
    float* vout = kout + (size_t)B_ * H_ * SKV_ * HD_;

    cudaFuncSetAttribute(k_flash_mma, cudaFuncAttributeMaxDynamicSharedMemorySize,
                         FLASH_SMEM_BYTES);
    cudaFuncSetAttribute(k_qkv_mma, cudaFuncAttributeMaxDynamicSharedMemorySize,
                         GEMM_SMEM_BYTES);
    cudaFuncSetAttribute(k_out_mma, cudaFuncAttributeMaxDynamicSharedMemorySize,
                         GEMM_SMEM_BYTES);

    k_cvt<<<2048, 256>>>((const float4*)x,     0, M_X * D_ / 8);
    k_cvt<<<2048, 256>>>((const float4*)qkv_w, 1, TD_ * D_ / 8);
    k_cvt<<<2048, 256>>>((const float4*)out_w, 2, D_ * D_ / 8);
    k_copy_past<<<4096, 256>>>((const float4*)past_k, (const float4*)past_v,
                               (float4*)kout, (float4*)vout);
    k_qkv_mma<<<dim3(TD_ / 128, M_X / 128), 256, GEMM_SMEM_BYTES>>>(qkv_b, kout, vout);
    k_flash_mma<<<dim3(S_ / 128, B_ * H_), 256, FLASH_SMEM_BYTES>>>();
    k_out_mma<<<dim3(D_ / 128, M_X / 128), 256, GEMM_SMEM_BYTES>>>(out_b, out);
}